// round 5
// baseline (speedup 1.0000x reference)
#include <cuda_runtime.h>

#define N_GENES 978
#define HID 2048
#define OUTD 100
#define MAXROWS 8192

// Scratch (allocation-free rule: __device__ globals)
__device__ float g_agg[(size_t)MAXROWS * N_GENES];   // 32 MB
__device__ float g_h[(size_t)MAXROWS * HID];         // 64 MB

// ---------------------------------------------------------------------------
// init: agg[i] = gcn_b[0]
// ---------------------------------------------------------------------------
__global__ void init_agg_kernel(const float* __restrict__ gcn_b, int n4) {
    float bv = gcn_b[0];
    float4 v = make_float4(bv, bv, bv, bv);
    float4* p = reinterpret_cast<float4*>(g_agg);
    int idx = blockIdx.x * blockDim.x + threadIdx.x;
    int stride = gridDim.x * blockDim.x;
    for (int i = idx; i < n4; i += stride) p[i] = v;
}

// ---------------------------------------------------------------------------
// scatter: agg[dst[e]] += x[src[e]] * w   (atomic segment-sum)
// Edges are INT32 (JAX without x64 silently downcasts int64 -> int32).
// 4 edges per thread via int4 vector loads on the index streams.
// ---------------------------------------------------------------------------
__global__ void scatter_kernel(const float* __restrict__ x,
                               const int* __restrict__ src,
                               const int* __restrict__ dst,
                               const float* __restrict__ gcn_w, int E4) {
    int i = blockIdx.x * blockDim.x + threadIdx.x;
    if (i >= E4) return;
    float w = __ldg(gcn_w);
    int4 s = reinterpret_cast<const int4*>(src)[i];
    int4 d = reinterpret_cast<const int4*>(dst)[i];
    atomicAdd(&g_agg[d.x], x[s.x] * w);
    atomicAdd(&g_agg[d.y], x[s.y] * w);
    atomicAdd(&g_agg[d.z], x[s.z] * w);
    atomicAdd(&g_agg[d.w], x[s.w] * w);
}

__global__ void scatter_tail_kernel(const float* __restrict__ x,
                                    const int* __restrict__ src,
                                    const int* __restrict__ dst,
                                    const float* __restrict__ gcn_w,
                                    int start, int E) {
    int i = start + blockIdx.x * blockDim.x + threadIdx.x;
    if (i >= E) return;
    float w = __ldg(gcn_w);
    atomicAdd(&g_agg[dst[i]], x[src[i]] * w);
}

// ---------------------------------------------------------------------------
// Generic fp32 tiled GEMM: C[M,Nact] = op(op_in(A[M,K]) @ B[K,Nact] + bias)
// SELA/SELC pick device-global scratch at compile time.
// ---------------------------------------------------------------------------
template<int BM, int BN, int BK, int TM, int TN,
         bool RELU_IN, bool RELU_OUT, int SELA, int SELC>
__global__ void __launch_bounds__((BM/TM)*(BN/TN))
gemm_kernel(const float* __restrict__ Ap, const float* __restrict__ B,
            const float* __restrict__ bias, float* __restrict__ Cp,
            int M, int Nact, int K)
{
    const float* A = (SELA == 1) ? g_agg : (SELA == 2) ? g_h : Ap;
    float*       C = (SELC == 2) ? g_h : Cp;

    constexpr int TX = BN / TN;
    constexpr int TY = BM / TM;
    constexpr int NT = TX * TY;

    __shared__ float As[BK][BM + 4];
    __shared__ float Bs[BK][BN];

    const int tid = threadIdx.x;
    const int tx = tid % TX;
    const int ty = tid / TX;
    const int bm = blockIdx.y * BM;
    const int bn = blockIdx.x * BN;
    const int m0 = ty * TM;
    const int n0 = tx * TN;

    float acc[TM][TN];
    #pragma unroll
    for (int i = 0; i < TM; i++)
        #pragma unroll
        for (int j = 0; j < TN; j++) acc[i][j] = 0.f;

    for (int k0 = 0; k0 < K; k0 += BK) {
        // --- load A tile (transposed into SMEM) ---
        #pragma unroll
        for (int i = tid; i < BM * BK; i += NT) {
            int m = i / BK;
            int k = i % BK;
            int gk = k0 + k;
            float v = 0.f;
            if (gk < K) v = A[(size_t)(bm + m) * K + gk];
            if (RELU_IN) v = fmaxf(v, 0.f);
            As[k][m] = v;
        }
        // --- load B tile (coalesced along N) ---
        #pragma unroll
        for (int i = tid; i < BK * BN; i += NT) {
            int k = i / BN;
            int n = i % BN;
            int gk = k0 + k;
            int gn = bn + n;
            float v = 0.f;
            if (gk < K && gn < Nact) v = B[(size_t)gk * Nact + gn];
            Bs[k][n] = v;
        }
        __syncthreads();

        #pragma unroll
        for (int kk = 0; kk < BK; ++kk) {
            float a[TM], b[TN];
            #pragma unroll
            for (int i = 0; i < TM; i++) a[i] = As[kk][m0 + i];
            #pragma unroll
            for (int j = 0; j < TN; j++) b[j] = Bs[kk][n0 + j];
            #pragma unroll
            for (int i = 0; i < TM; i++)
                #pragma unroll
                for (int j = 0; j < TN; j++)
                    acc[i][j] = fmaf(a[i], b[j], acc[i][j]);
        }
        __syncthreads();
    }

    // --- epilogue: bias (+ optional relu), store ---
    #pragma unroll
    for (int i = 0; i < TM; i++) {
        int gm = bm + m0 + i;
        #pragma unroll
        for (int j = 0; j < TN; j++) {
            int gn = bn + n0 + j;
            if (gn < Nact) {
                float v = acc[i][j] + bias[gn];
                if (RELU_OUT) v = fmaxf(v, 0.f);
                C[(size_t)gm * Nact + gn] = v;
            }
        }
    }
}

// ---------------------------------------------------------------------------
// launch
// ---------------------------------------------------------------------------
extern "C" void kernel_launch(void* const* d_in, const int* in_sizes, int n_in,
                              void* d_out, int out_size) {
    const float* inputs = (const float*)d_in[0];
    const int*   edges  = (const int*)d_in[1];    // int32! (JAX x64 disabled)
    const float* gcn_w  = (const float*)d_in[2];
    const float* gcn_b  = (const float*)d_in[3];
    const float* W1     = (const float*)d_in[4];
    const float* b1     = (const float*)d_in[5];
    const float* W2     = (const float*)d_in[6];
    const float* b2     = (const float*)d_in[7];
    float*       out    = (float*)d_out;

    const int NN = in_sizes[0];          // B * 978 node count
    const int E  = in_sizes[1] / 2;      // edge count (edges is [2, E])
    const int M  = NN / N_GENES;         // batch rows (8192)

    const int* src = edges;
    const int* dst = edges + E;

    // 1) agg = gcn_b
    init_agg_kernel<<<1184, 256>>>(gcn_b, NN / 4);

    // 2) agg[dst] += inputs_flat[src] * gcn_w
    {
        int E4 = E / 4;
        if (E4 > 0)
            scatter_kernel<<<(E4 + 255) / 256, 256>>>(inputs, src, dst, gcn_w, E4);
        int rem = E - E4 * 4;
        if (rem > 0)
            scatter_tail_kernel<<<1, 256>>>(inputs, src, dst, gcn_w, E4 * 4, E);
    }

    // 3) h = relu(relu(agg) @ W1 + b1)   [M,978]x[978,2048]
    {
        dim3 grid(HID / 128, M / 128);
        gemm_kernel<128, 128, 16, 8, 8, true, true, 1, 2>
            <<<grid, 256>>>(nullptr, W1, b1, nullptr, M, HID, N_GENES);
    }

    // 4) out = h @ W2 + b2               [M,2048]x[2048,100]
    {
        dim3 grid((OUTD + 111) / 112, M / 128);
        gemm_kernel<128, 112, 32, 8, 7, false, false, 2, 0>
            <<<grid, 256>>>(nullptr, W2, b2, out, M, OUTD, HID);
    }
}

// round 6
// speedup vs baseline: 3.0913x; 3.0913x over previous
#include <cuda_runtime.h>
#include <cstdint>

#define N_GENES 978
#define AKP     992     // padded K stride for g_agg / g_W1t (16B-aligned rows)
#define HID     2048
#define OUTD    100
#define OUTP    128     // padded N for W2^T
#define MROWS   8192

#define BM  256
#define BN  128
#define BK  32
#define BKP 36          // smem row pad (floats) -> conflict-free ldmatrix

// Scratch (allocation-free rule: __device__ globals)
__device__ float g_agg[(size_t)MROWS * AKP];   // ~32.5 MB
__device__ float g_h  [(size_t)MROWS * HID];   // 64 MB
__device__ float g_W1t[(size_t)HID * AKP];     // 8.1 MB  [n][k] tf32-rounded
__device__ float g_W2t[(size_t)OUTP * HID];    // 1 MB    [n][k] tf32-rounded, zero-padded n>=100

__device__ __forceinline__ float to_tf32(float x) {
    float r; asm("cvt.rna.tf32.f32 %0, %1;" : "=f"(r) : "f"(x)); return r;
}

// ---------------------------------------------------------------------------
// init: agg[:] = gcn_b (padding cols too; harmless, W1t pad is zero)
// ---------------------------------------------------------------------------
__global__ void init_agg_kernel(const float* __restrict__ gcn_b, int n4) {
    float bv = gcn_b[0];
    float4 v = make_float4(bv, bv, bv, bv);
    float4* p = reinterpret_cast<float4*>(g_agg);
    int idx = blockIdx.x * blockDim.x + threadIdx.x;
    int stride = gridDim.x * blockDim.x;
    for (int i = idx; i < n4; i += stride) p[i] = v;
}

// ---------------------------------------------------------------------------
// scatter: agg[remap(dst)] += x[src] * w  (edges are int32)
// ---------------------------------------------------------------------------
__device__ __forceinline__ void scat1(const float* x, float w, int s, int d) {
    int r = d / N_GENES;
    int c = d - r * N_GENES;
    atomicAdd(&g_agg[(size_t)r * AKP + c], x[s] * w);
}

__global__ void scatter_kernel(const float* __restrict__ x,
                               const int* __restrict__ src,
                               const int* __restrict__ dst,
                               const float* __restrict__ gcn_w, int E4) {
    int i = blockIdx.x * blockDim.x + threadIdx.x;
    if (i >= E4) return;
    float w = __ldg(gcn_w);
    int4 s = reinterpret_cast<const int4*>(src)[i];
    int4 d = reinterpret_cast<const int4*>(dst)[i];
    scat1(x, w, s.x, d.x);
    scat1(x, w, s.y, d.y);
    scat1(x, w, s.z, d.z);
    scat1(x, w, s.w, d.w);
}

__global__ void scatter_tail_kernel(const float* __restrict__ x,
                                    const int* __restrict__ src,
                                    const int* __restrict__ dst,
                                    const float* __restrict__ gcn_w,
                                    int start, int E) {
    int i = start + blockIdx.x * blockDim.x + threadIdx.x;
    if (i >= E) return;
    scat1(x, __ldg(gcn_w), src[i], dst[i]);
}

// ---------------------------------------------------------------------------
// relu + tf32-round over g_agg (in place)
// ---------------------------------------------------------------------------
__global__ void relu_round_kernel(int n4) {
    float4* p = reinterpret_cast<float4*>(g_agg);
    int idx = blockIdx.x * blockDim.x + threadIdx.x;
    int stride = gridDim.x * blockDim.x;
    for (int i = idx; i < n4; i += stride) {
        float4 v = p[i];
        v.x = to_tf32(fmaxf(v.x, 0.f));
        v.y = to_tf32(fmaxf(v.y, 0.f));
        v.z = to_tf32(fmaxf(v.z, 0.f));
        v.w = to_tf32(fmaxf(v.w, 0.f));
        p[i] = v;
    }
}

// ---------------------------------------------------------------------------
// transposes (tf32-rounded, zero-padded)
// ---------------------------------------------------------------------------
__global__ void transpose_w1(const float* __restrict__ W) {  // W [978][2048] -> g_W1t [2048][992]
    __shared__ float t[32][33];
    int kb = blockIdx.x * 32, nb = blockIdx.y * 32;
    int tx = threadIdx.x, ty = threadIdx.y;   // block (32,8)
    for (int i = ty; i < 32; i += 8) {
        int k = kb + i;
        float v = (k < N_GENES) ? W[(size_t)k * HID + (nb + tx)] : 0.f;
        t[i][tx] = to_tf32(v);
    }
    __syncthreads();
    for (int i = ty; i < 32; i += 8) {
        g_W1t[(size_t)(nb + i) * AKP + (kb + tx)] = t[tx][i];
    }
}

__global__ void transpose_w2(const float* __restrict__ W) {  // W [2048][100] -> g_W2t [128][2048]
    __shared__ float t[32][33];
    int kb = blockIdx.x * 32, nb = blockIdx.y * 32;
    int tx = threadIdx.x, ty = threadIdx.y;
    for (int i = ty; i < 32; i += 8) {
        int n = nb + tx;
        float v = (n < OUTD) ? W[(size_t)(kb + i) * OUTD + n] : 0.f;
        t[i][tx] = to_tf32(v);
    }
    __syncthreads();
    for (int i = ty; i < 32; i += 8) {
        g_W2t[(size_t)(nb + i) * HID + (kb + tx)] = t[tx][i];
    }
}

// ---------------------------------------------------------------------------
// out init: out[m][j] = b2[j]
// ---------------------------------------------------------------------------
__global__ void out_init_kernel(float* __restrict__ out, const float* __restrict__ b2, int total) {
    int i = blockIdx.x * blockDim.x + threadIdx.x;
    if (i < total) out[i] = b2[i % OUTD];
}

// ---------------------------------------------------------------------------
// TF32 tensor-core GEMM: C[M,N] = A[M,K] @ B[N,K]^T
//   A, B pre-rounded to tf32; fragments via ldmatrix.b16 (8x8 b16 == 8x4 tf32)
//   EPI=1: C=g_h, v = tf32(relu(acc + bias))          (GEMM1)
//   EPI=2: atomicAdd into Cout (guard n<OUTD), split-K (GEMM2)
// ---------------------------------------------------------------------------
__device__ __forceinline__ void cp16(uint32_t s, const float* g) {
    asm volatile("cp.async.cg.shared.global [%0], [%1], 16;" :: "r"(s), "l"(g));
}
__device__ __forceinline__ void ldsm4(uint32_t a, uint32_t& r0, uint32_t& r1,
                                      uint32_t& r2, uint32_t& r3) {
    asm volatile("ldmatrix.sync.aligned.m8n8.x4.shared.b16 {%0,%1,%2,%3}, [%4];"
                 : "=r"(r0), "=r"(r1), "=r"(r2), "=r"(r3) : "r"(a));
}
__device__ __forceinline__ void mma_tf32(float* c, const uint32_t* a, uint32_t b0, uint32_t b1) {
    asm volatile("mma.sync.aligned.m16n8k8.row.col.f32.tf32.tf32.f32 "
                 "{%0,%1,%2,%3},{%4,%5,%6,%7},{%8,%9},{%0,%1,%2,%3};"
                 : "+f"(c[0]), "+f"(c[1]), "+f"(c[2]), "+f"(c[3])
                 : "r"(a[0]), "r"(a[1]), "r"(a[2]), "r"(a[3]), "r"(b0), "r"(b1));
}

template<int LDA, int LDB, int EPI, int SELA, int SELB>
__global__ void __launch_bounds__(256, 1)
mma_gemm(const float* __restrict__ bias, float* __restrict__ Cout, int kIters) {
    const float* A = (SELA == 1) ? g_agg : g_h;
    const float* B = (SELB == 1) ? g_W1t : g_W2t;

    extern __shared__ float smem[];
    float* AsBase = smem;                       // 2 stages of BM*BKP
    float* BsBase = smem + 2 * BM * BKP;        // 2 stages of BN*BKP

    const int tid  = threadIdx.x;
    const int wid  = tid >> 5;
    const int lane = tid & 31;
    const int bm = blockIdx.y * BM;
    const int bn = blockIdx.x * BN;
    const int k0base = blockIdx.z * kIters * BK;

    const int m0w = (wid >> 1) * 64;
    const int n0w = (wid & 1) * 64;
    const int grp = lane >> 2, t4 = lane & 3;

    const uint32_t s_As = (uint32_t)__cvta_generic_to_shared(AsBase);
    const uint32_t s_Bs = (uint32_t)__cvta_generic_to_shared(BsBase);
    const uint32_t AS_B = BM * BKP * 4;
    const uint32_t BS_B = BN * BKP * 4;

    // per-lane ldmatrix row offsets
    const int tI = lane >> 3, rI = lane & 7;
    const uint32_t a_off = (uint32_t)((m0w + (tI & 1) * 8 + rI) * BKP + (tI >> 1) * 4) * 4;
    const uint32_t b_off = (uint32_t)((n0w + (tI >> 1) * 8 + rI) * BKP + (tI & 1) * 4) * 4;

    float acc[4][8][4];
    #pragma unroll
    for (int a = 0; a < 4; a++)
        #pragma unroll
        for (int b = 0; b < 8; b++)
            #pragma unroll
            for (int c = 0; c < 4; c++) acc[a][b][c] = 0.f;

    auto load_tile = [&](int stage, int k0) {
        uint32_t sa = s_As + stage * AS_B;
        #pragma unroll
        for (int i = 0; i < 8; i++) {
            int idx = tid + i * 256;
            int m = idx >> 3, kq = idx & 7;
            cp16(sa + (uint32_t)(m * BKP + kq * 4) * 4,
                 A + (size_t)(bm + m) * LDA + k0 + kq * 4);
        }
        uint32_t sb = s_Bs + stage * BS_B;
        #pragma unroll
        for (int i = 0; i < 4; i++) {
            int idx = tid + i * 256;
            int n = idx >> 3, kq = idx & 7;
            cp16(sb + (uint32_t)(n * BKP + kq * 4) * 4,
                 B + (size_t)(bn + n) * LDB + k0 + kq * 4);
        }
        asm volatile("cp.async.commit_group;");
    };

    load_tile(0, k0base);

    for (int it = 0; it < kIters; ++it) {
        int st = it & 1;
        if (it + 1 < kIters) {
            load_tile((it + 1) & 1, k0base + (it + 1) * BK);
            asm volatile("cp.async.wait_group 1;");
        } else {
            asm volatile("cp.async.wait_group 0;");
        }
        __syncthreads();

        #pragma unroll
        for (int ks = 0; ks < 4; ++ks) {
            uint32_t af[4][4];
            #pragma unroll
            for (int mt = 0; mt < 4; ++mt)
                ldsm4(s_As + st * AS_B + a_off + (uint32_t)(mt * 16 * BKP + ks * 8) * 4,
                      af[mt][0], af[mt][1], af[mt][2], af[mt][3]);
            uint32_t bf[4][4];
            #pragma unroll
            for (int np = 0; np < 4; ++np)
                ldsm4(s_Bs + st * BS_B + b_off + (uint32_t)(np * 16 * BKP + ks * 8) * 4,
                      bf[np][0], bf[np][1], bf[np][2], bf[np][3]);
            #pragma unroll
            for (int mt = 0; mt < 4; ++mt)
                #pragma unroll
                for (int nt = 0; nt < 8; ++nt)
                    mma_tf32(acc[mt][nt], af[mt],
                             bf[nt >> 1][(nt & 1) * 2], bf[nt >> 1][(nt & 1) * 2 + 1]);
        }
        __syncthreads();
    }

    // epilogue
    #pragma unroll
    for (int mt = 0; mt < 4; ++mt) {
        int gm0 = bm + m0w + mt * 16 + grp;
        #pragma unroll
        for (int nt = 0; nt < 8; ++nt) {
            int gn = bn + n0w + nt * 8 + t4 * 2;
            if (EPI == 1) {
                float b0v = bias[gn], b1v = bias[gn + 1];
                float v0 = to_tf32(fmaxf(acc[mt][nt][0] + b0v, 0.f));
                float v1 = to_tf32(fmaxf(acc[mt][nt][1] + b1v, 0.f));
                float v2 = to_tf32(fmaxf(acc[mt][nt][2] + b0v, 0.f));
                float v3 = to_tf32(fmaxf(acc[mt][nt][3] + b1v, 0.f));
                *reinterpret_cast<float2*>(&g_h[(size_t)gm0 * HID + gn])       = make_float2(v0, v1);
                *reinterpret_cast<float2*>(&g_h[(size_t)(gm0 + 8) * HID + gn]) = make_float2(v2, v3);
            } else {
                if (gn < OUTD) {   // gn even, so gn+1 < OUTD too
                    atomicAdd(&Cout[(size_t)gm0 * OUTD + gn],           acc[mt][nt][0]);
                    atomicAdd(&Cout[(size_t)gm0 * OUTD + gn + 1],       acc[mt][nt][1]);
                    atomicAdd(&Cout[(size_t)(gm0 + 8) * OUTD + gn],     acc[mt][nt][2]);
                    atomicAdd(&Cout[(size_t)(gm0 + 8) * OUTD + gn + 1], acc[mt][nt][3]);
                }
            }
        }
    }
}

// ---------------------------------------------------------------------------
// launch
// ---------------------------------------------------------------------------
extern "C" void kernel_launch(void* const* d_in, const int* in_sizes, int n_in,
                              void* d_out, int out_size) {
    const float* inputs = (const float*)d_in[0];
    const int*   edges  = (const int*)d_in[1];    // int32 (JAX x64 disabled)
    const float* gcn_w  = (const float*)d_in[2];
    const float* gcn_b  = (const float*)d_in[3];
    const float* W1     = (const float*)d_in[4];
    const float* b1     = (const float*)d_in[5];
    const float* W2     = (const float*)d_in[6];
    const float* b2     = (const float*)d_in[7];
    float*       out    = (float*)d_out;

    const int E = in_sizes[1] / 2;

    const int* src = edges;
    const int* dst = edges + E;

    constexpr int SMEM_BYTES = (2 * BM * BKP + 2 * BN * BKP) * 4;  // 110592

    cudaFuncSetAttribute(mma_gemm<AKP, AKP, 1, 1, 1>,
                         cudaFuncAttributeMaxDynamicSharedMemorySize, SMEM_BYTES);
    cudaFuncSetAttribute(mma_gemm<HID, HID, 2, 2, 2>,
                         cudaFuncAttributeMaxDynamicSharedMemorySize, SMEM_BYTES);

    // 1) agg = bias (padded)
    init_agg_kernel<<<1184, 256>>>(gcn_b, MROWS * AKP / 4);

    // 2) scatter
    {
        int E4 = E / 4;
        if (E4 > 0)
            scatter_kernel<<<(E4 + 255) / 256, 256>>>(inputs, src, dst, gcn_w, E4);
        if (E - E4 * 4 > 0)
            scatter_tail_kernel<<<1, 256>>>(inputs, src, dst, gcn_w, E4 * 4, E);
    }

    // 3) relu + tf32 round on agg
    relu_round_kernel<<<1184, 256>>>(MROWS * AKP / 4);

    // 4) weight transposes (tf32-rounded, zero-padded)
    transpose_w1<<<dim3(AKP / 32, HID / 32), dim3(32, 8)>>>(W1);
    transpose_w2<<<dim3(HID / 32, OUTP / 32), dim3(32, 8)>>>(W2);

    // 5) out = b2 (broadcast) for split-K accumulation
    out_init_kernel<<<(MROWS * OUTD + 255) / 256, 256>>>(out, b2, MROWS * OUTD);

    // 6) GEMM1: h = tf32(relu(relu(agg) @ W1 + b1))   M=8192,N=2048,K=978(pad 992)
    mma_gemm<AKP, AKP, 1, 1, 1>
        <<<dim3(HID / BN, MROWS / BM, 1), 256, SMEM_BYTES>>>(b1, nullptr, AKP / BK);

    // 7) GEMM2: out += h @ W2  (split-K=4)            M=8192,N=100(pad 128),K=2048
    mma_gemm<HID, HID, 2, 2, 2>
        <<<dim3(1, MROWS / BM, 4), 256, SMEM_BYTES>>>(nullptr, out, HID / BK / 4);
}

// round 9
// speedup vs baseline: 3.2685x; 1.0573x over previous
#include <cuda_runtime.h>
#include <cstdint>

#define N_GENES 978
#define AKP     992     // padded K stride for g_agg / g_W1t (16B-aligned rows)
#define HID     2048
#define OUTD    100
#define OUTP    128     // padded N for W2^T
#define MROWS   8192

#define BK   32
#define BKP  36         // smem row pad (floats) -> conflict-free ldmatrix
#define NSTG 4          // cp.async pipeline stages

// Scratch (allocation-free rule: __device__ globals)
__device__ float g_agg[(size_t)MROWS * AKP];
__device__ float g_h  [(size_t)MROWS * HID];
__device__ float g_W1t[(size_t)HID * AKP];
__device__ float g_W2t[(size_t)OUTP * HID];

__device__ __forceinline__ float to_tf32(float x) {
    float r; asm("cvt.rna.tf32.f32 %0, %1;" : "=f"(r) : "f"(x)); return r;
}
__device__ __forceinline__ uint32_t smem_u32(const void* p) {
    return (uint32_t)__cvta_generic_to_shared(p);
}
__device__ __forceinline__ void cp16(uint32_t s, const float* g) {
    asm volatile("cp.async.cg.shared.global [%0], [%1], 16;" :: "r"(s), "l"(g));
}
__device__ __forceinline__ void ldsm4(uint32_t a, uint32_t& r0, uint32_t& r1,
                                      uint32_t& r2, uint32_t& r3) {
    asm volatile("ldmatrix.sync.aligned.m8n8.x4.shared.b16 {%0,%1,%2,%3}, [%4];"
                 : "=r"(r0), "=r"(r1), "=r"(r2), "=r"(r3) : "r"(a));
}
__device__ __forceinline__ void mma_tf32(float* c, const uint32_t* a, uint32_t b0, uint32_t b1) {
    asm volatile("mma.sync.aligned.m16n8k8.row.col.f32.tf32.tf32.f32 "
                 "{%0,%1,%2,%3},{%4,%5,%6,%7},{%8,%9},{%0,%1,%2,%3};"
                 : "+f"(c[0]), "+f"(c[1]), "+f"(c[2]), "+f"(c[3])
                 : "r"(a[0]), "r"(a[1]), "r"(a[2]), "r"(a[3]), "r"(b0), "r"(b1));
}

// ===========================================================================
// init / scatter / prep
// ===========================================================================
__global__ void init_agg_kernel(const float* __restrict__ gcn_b, int n4) {
    float bv = gcn_b[0];
    float4 v = make_float4(bv, bv, bv, bv);
    float4* p = reinterpret_cast<float4*>(g_agg);
    int idx = blockIdx.x * blockDim.x + threadIdx.x;
    int stride = gridDim.x * blockDim.x;
    for (int i = idx; i < n4; i += stride) p[i] = v;
}

__device__ __forceinline__ void scat1(const float* x, float w, int s, int d) {
    int r = d / N_GENES;
    int c = d - r * N_GENES;
    atomicAdd(&g_agg[(size_t)r * AKP + c], x[s] * w);
}

__global__ void scatter_kernel(const float* __restrict__ x,
                               const int* __restrict__ src,
                               const int* __restrict__ dst,
                               const float* __restrict__ gcn_w, int E8) {
    int i = blockIdx.x * blockDim.x + threadIdx.x;
    if (i >= E8) return;
    float w = __ldg(gcn_w);
    int4 s0 = reinterpret_cast<const int4*>(src)[2 * i];
    int4 s1 = reinterpret_cast<const int4*>(src)[2 * i + 1];
    int4 d0 = reinterpret_cast<const int4*>(dst)[2 * i];
    int4 d1 = reinterpret_cast<const int4*>(dst)[2 * i + 1];
    scat1(x, w, s0.x, d0.x);
    scat1(x, w, s0.y, d0.y);
    scat1(x, w, s0.z, d0.z);
    scat1(x, w, s0.w, d0.w);
    scat1(x, w, s1.x, d1.x);
    scat1(x, w, s1.y, d1.y);
    scat1(x, w, s1.z, d1.z);
    scat1(x, w, s1.w, d1.w);
}

__global__ void scatter_tail_kernel(const float* __restrict__ x,
                                    const int* __restrict__ src,
                                    const int* __restrict__ dst,
                                    const float* __restrict__ gcn_w,
                                    int start, int E) {
    int i = start + blockIdx.x * blockDim.x + threadIdx.x;
    if (i >= E) return;
    scat1(x, __ldg(gcn_w), src[i], dst[i]);
}

__global__ void relu_round_kernel(int n4) {
    float4* p = reinterpret_cast<float4*>(g_agg);
    int idx = blockIdx.x * blockDim.x + threadIdx.x;
    int stride = gridDim.x * blockDim.x;
    for (int i = idx; i < n4; i += stride) {
        float4 v = p[i];
        v.x = to_tf32(fmaxf(v.x, 0.f));
        v.y = to_tf32(fmaxf(v.y, 0.f));
        v.z = to_tf32(fmaxf(v.z, 0.f));
        v.w = to_tf32(fmaxf(v.w, 0.f));
        p[i] = v;
    }
}

__global__ void transpose_w1(const float* __restrict__ W) {  // [978][2048] -> [2048][992]
    __shared__ float t[32][33];
    int kb = blockIdx.x * 32, nb = blockIdx.y * 32;
    int tx = threadIdx.x, ty = threadIdx.y;
    for (int i = ty; i < 32; i += 8) {
        int k = kb + i;
        float v = (k < N_GENES) ? W[(size_t)k * HID + (nb + tx)] : 0.f;
        t[i][tx] = to_tf32(v);
    }
    __syncthreads();
    for (int i = ty; i < 32; i += 8)
        g_W1t[(size_t)(nb + i) * AKP + (kb + tx)] = t[tx][i];
}

__global__ void transpose_w2(const float* __restrict__ W) {  // [2048][100] -> [128][2048]
    __shared__ float t[32][33];
    int kb = blockIdx.x * 32, nb = blockIdx.y * 32;
    int tx = threadIdx.x, ty = threadIdx.y;
    for (int i = ty; i < 32; i += 8) {
        int n = nb + tx;
        float v = (n < OUTD) ? W[(size_t)(kb + i) * OUTD + n] : 0.f;
        t[i][tx] = to_tf32(v);
    }
    __syncthreads();
    for (int i = ty; i < 32; i += 8)
        g_W2t[(size_t)(nb + i) * HID + (kb + tx)] = t[tx][i];
}

__global__ void out_init_kernel(float* __restrict__ out, const float* __restrict__ b2, int total) {
    int i = blockIdx.x * blockDim.x + threadIdx.x;
    if (i < total) out[i] = b2[i % OUTD];
}

// ===========================================================================
// Unified tf32 mma.sync GEMM, 4-stage cp.async, 256 threads, 8 warps (4M x 2N)
//   warp tile: (BMp/4) x 64, MT = BMp/64
//   EPI=1: C = g_h, v = tf32(relu(acc + bias))     (GEMM1: A=g_agg, B=g_W1t)
//   EPI=2: atomicAdd into Cout, guard n < OUTD     (GEMM2: A=g_h,   B=g_W2t)
// ===========================================================================
template<int BMp, int BNp, int MT, int EPI, int LDA_, int LDB_>
__global__ void __launch_bounds__(256, 1)
mma_gemm(const float* __restrict__ bias, float* __restrict__ Cout, int kIters) {
    const float* A = (EPI == 1) ? g_agg : g_h;
    const float* B = (EPI == 1) ? g_W1t : g_W2t;

    extern __shared__ float smem[];
    constexpr uint32_t AS_B    = BMp * BKP * 4;
    constexpr uint32_t BS_B    = BNp * BKP * 4;
    constexpr uint32_t STAGE_B = AS_B + BS_B;

    const int tid  = threadIdx.x;
    const int wid  = tid >> 5;
    const int lane = tid & 31;
    const int bm = blockIdx.y * BMp;
    const int bn = blockIdx.x * BNp;
    const int k0base = blockIdx.z * kIters * BK;

    const int m0w = (wid >> 1) * (BMp / 4);
    const int n0w = (wid & 1) * 64;
    const int grp = lane >> 2, t4 = lane & 3;

    const uint32_t s_base = smem_u32(smem);

    const int tI = lane >> 3, rI = lane & 7;
    const uint32_t a_off = (uint32_t)((m0w + (tI & 1) * 8 + rI) * BKP + (tI >> 1) * 4) * 4;
    const uint32_t b_off = (uint32_t)((n0w + (tI >> 1) * 8 + rI) * BKP + (tI & 1) * 4) * 4;

    float acc[MT][8][4];
    #pragma unroll
    for (int a = 0; a < MT; a++)
        #pragma unroll
        for (int b = 0; b < 8; b++)
            #pragma unroll
            for (int c = 0; c < 4; c++) acc[a][b][c] = 0.f;

    auto load_tile = [&](int stage, int k0) {
        uint32_t sa = s_base + stage * STAGE_B;
        #pragma unroll
        for (int i = 0; i < BMp / 32; i++) {
            int idx = tid + i * 256;
            int m = idx >> 3, kq = idx & 7;
            cp16(sa + (uint32_t)(m * BKP + kq * 4) * 4,
                 A + (size_t)(bm + m) * LDA_ + k0 + kq * 4);
        }
        uint32_t sb = sa + AS_B;
        #pragma unroll
        for (int i = 0; i < BNp / 32; i++) {
            int idx = tid + i * 256;
            int n = idx >> 3, kq = idx & 7;
            cp16(sb + (uint32_t)(n * BKP + kq * 4) * 4,
                 B + (size_t)(bn + n) * LDB_ + k0 + kq * 4);
        }
    };

    // prologue: fill stages 0..NSTG-2
    #pragma unroll
    for (int p = 0; p < NSTG - 1; ++p) {
        if (p < kIters) load_tile(p, k0base + p * BK);
        asm volatile("cp.async.commit_group;");
    }

    for (int it = 0; it < kIters; ++it) {
        int st = it & (NSTG - 1);
        asm volatile("cp.async.wait_group %0;" :: "n"(NSTG - 2));
        __syncthreads();

        #pragma unroll
        for (int ks = 0; ks < 4; ++ks) {
            uint32_t af[MT][4];
            #pragma unroll
            for (int mt = 0; mt < MT; ++mt)
                ldsm4(s_base + st * STAGE_B + a_off + (uint32_t)(mt * 16 * BKP + ks * 8) * 4,
                      af[mt][0], af[mt][1], af[mt][2], af[mt][3]);
            uint32_t bf[4][4];
            #pragma unroll
            for (int np = 0; np < 4; ++np)
                ldsm4(s_base + st * STAGE_B + AS_B + b_off + (uint32_t)(np * 16 * BKP + ks * 8) * 4,
                      bf[np][0], bf[np][1], bf[np][2], bf[np][3]);
            #pragma unroll
            for (int mt = 0; mt < MT; ++mt)
                #pragma unroll
                for (int nt = 0; nt < 8; ++nt)
                    mma_tf32(acc[mt][nt], af[mt],
                             bf[nt >> 1][(nt & 1) * 2], bf[nt >> 1][(nt & 1) * 2 + 1]);
        }

        if (it + NSTG - 1 < kIters)
            load_tile((it + NSTG - 1) & (NSTG - 1), k0base + (it + NSTG - 1) * BK);
        asm volatile("cp.async.commit_group;");
    }

    // epilogue
    #pragma unroll
    for (int mt = 0; mt < MT; ++mt) {
        int gm0 = bm + m0w + mt * 16 + grp;
        #pragma unroll
        for (int nt = 0; nt < 8; ++nt) {
            int gn = bn + n0w + nt * 8 + t4 * 2;
            if (EPI == 1) {
                float b0v = bias[gn], b1v = bias[gn + 1];
                float v0 = to_tf32(fmaxf(acc[mt][nt][0] + b0v, 0.f));
                float v1 = to_tf32(fmaxf(acc[mt][nt][1] + b1v, 0.f));
                float v2 = to_tf32(fmaxf(acc[mt][nt][2] + b0v, 0.f));
                float v3 = to_tf32(fmaxf(acc[mt][nt][3] + b1v, 0.f));
                *reinterpret_cast<float2*>(&g_h[(size_t)gm0 * HID + gn])       = make_float2(v0, v1);
                *reinterpret_cast<float2*>(&g_h[(size_t)(gm0 + 8) * HID + gn]) = make_float2(v2, v3);
            } else {
                if (gn < OUTD) {   // gn even, so gn+1 < OUTD too
                    atomicAdd(&Cout[(size_t)gm0 * OUTD + gn],           acc[mt][nt][0]);
                    atomicAdd(&Cout[(size_t)gm0 * OUTD + gn + 1],       acc[mt][nt][1]);
                    atomicAdd(&Cout[(size_t)(gm0 + 8) * OUTD + gn],     acc[mt][nt][2]);
                    atomicAdd(&Cout[(size_t)(gm0 + 8) * OUTD + gn + 1], acc[mt][nt][3]);
                }
            }
        }
    }
}

// ===========================================================================
// launch
// ===========================================================================
extern "C" void kernel_launch(void* const* d_in, const int* in_sizes, int n_in,
                              void* d_out, int out_size) {
    const float* inputs = (const float*)d_in[0];
    const int*   edges  = (const int*)d_in[1];    // int32 (JAX x64 disabled)
    const float* gcn_w  = (const float*)d_in[2];
    const float* gcn_b  = (const float*)d_in[3];
    const float* W1     = (const float*)d_in[4];
    const float* b1     = (const float*)d_in[5];
    const float* W2     = (const float*)d_in[6];
    const float* b2     = (const float*)d_in[7];
    float*       out    = (float*)d_out;

    const int E = in_sizes[1] / 2;
    const int* src = edges;
    const int* dst = edges + E;

    constexpr int G1_SMEM = NSTG * (256 * BKP + 128 * BKP) * 4;   // 221184
    constexpr int G2_SMEM = NSTG * (128 * BKP + 128 * BKP) * 4;   // 147456

    cudaFuncSetAttribute(mma_gemm<256, 128, 4, 1, AKP, AKP>,
                         cudaFuncAttributeMaxDynamicSharedMemorySize, G1_SMEM);
    cudaFuncSetAttribute(mma_gemm<128, 128, 2, 2, HID, HID>,
                         cudaFuncAttributeMaxDynamicSharedMemorySize, G2_SMEM);

    // 1) agg = bias (padded)
    init_agg_kernel<<<1184, 256>>>(gcn_b, MROWS * AKP / 4);

    // 2) scatter (8 edges per thread)
    {
        int E8 = E / 8;
        if (E8 > 0)
            scatter_kernel<<<(E8 + 255) / 256, 256>>>(inputs, src, dst, gcn_w, E8);
        if (E - E8 * 8 > 0)
            scatter_tail_kernel<<<1, 256>>>(inputs, src, dst, gcn_w, E8 * 8, E);
    }

    // 3) relu + tf32 round on agg
    relu_round_kernel<<<1184, 256>>>(MROWS * AKP / 4);

    // 4) weight prep
    transpose_w1<<<dim3(AKP / 32, HID / 32), dim3(32, 8)>>>(W1);
    transpose_w2<<<dim3(HID / 32, OUTP / 32), dim3(32, 8)>>>(W2);

    // 5) out = b2 (broadcast) for split-K accumulation
    out_init_kernel<<<(MROWS * OUTD + 255) / 256, 256>>>(out, b2, MROWS * OUTD);

    // 6) GEMM1: h = tf32(relu(relu(agg) @ W1 + b1))   grid (16, 32)
    mma_gemm<256, 128, 4, 1, AKP, AKP>
        <<<dim3(HID / 128, MROWS / 256), 256, G1_SMEM>>>(b1, nullptr, AKP / BK);

    // 7) GEMM2: out += h @ W2   split-K=4, grid (1, 64, 4) = 256 CTAs
    mma_gemm<128, 128, 2, 2, HID, HID>
        <<<dim3(1, MROWS / 128, 4), 256, G2_SMEM>>>(nullptr, out, HID / BK / 4);
}

// round 12
// speedup vs baseline: 3.3530x; 1.0259x over previous
#include <cuda_runtime.h>
#include <cstdint>

#define N_GENES 978
#define AKP     992     // padded K stride for g_agg / g_W1t (16B-aligned rows)
#define HID     2048
#define OUTD    100
#define OUTP    128     // padded N for W2^T
#define MROWS   8192

#define BK   32
#define BKP  36         // smem row pad (floats) -> conflict-free ldmatrix
#define NSTG 3          // cp.async pipeline stages (3 so 2 CTAs/SM fit in smem)

// Scratch (allocation-free rule: __device__ globals)
__device__ float g_agg[(size_t)MROWS * AKP];
__device__ float g_h  [(size_t)MROWS * HID];
__device__ float g_W1t[(size_t)HID * AKP];
__device__ float g_W2t[(size_t)OUTP * HID];

__device__ __forceinline__ float to_tf32(float x) {
    float r; asm("cvt.rna.tf32.f32 %0, %1;" : "=f"(r) : "f"(x)); return r;
}
__device__ __forceinline__ uint32_t smem_u32(const void* p) {
    return (uint32_t)__cvta_generic_to_shared(p);
}
__device__ __forceinline__ void cp16(uint32_t s, const float* g) {
    asm volatile("cp.async.cg.shared.global [%0], [%1], 16;" :: "r"(s), "l"(g));
}
__device__ __forceinline__ void ldsm4(uint32_t a, uint32_t& r0, uint32_t& r1,
                                      uint32_t& r2, uint32_t& r3) {
    asm volatile("ldmatrix.sync.aligned.m8n8.x4.shared.b16 {%0,%1,%2,%3}, [%4];"
                 : "=r"(r0), "=r"(r1), "=r"(r2), "=r"(r3) : "r"(a));
}
__device__ __forceinline__ void mma_tf32(float* c, const uint32_t* a, uint32_t b0, uint32_t b1) {
    asm volatile("mma.sync.aligned.m16n8k8.row.col.f32.tf32.tf32.f32 "
                 "{%0,%1,%2,%3},{%4,%5,%6,%7},{%8,%9},{%0,%1,%2,%3};"
                 : "+f"(c[0]), "+f"(c[1]), "+f"(c[2]), "+f"(c[3])
                 : "r"(a[0]), "r"(a[1]), "r"(a[2]), "r"(a[3]), "r"(b0), "r"(b1));
}

// ===========================================================================
// init / scatter / prep
// ===========================================================================
__global__ void init_agg_kernel(const float* __restrict__ gcn_b, int n4) {
    float bv = gcn_b[0];
    float4 v = make_float4(bv, bv, bv, bv);
    float4* p = reinterpret_cast<float4*>(g_agg);
    int idx = blockIdx.x * blockDim.x + threadIdx.x;
    int stride = gridDim.x * blockDim.x;
    for (int i = idx; i < n4; i += stride) p[i] = v;
}

__device__ __forceinline__ void scat1(const float* x, float w, int s, int d) {
    int r = d / N_GENES;
    int c = d - r * N_GENES;
    atomicAdd(&g_agg[(size_t)r * AKP + c], x[s] * w);
}

__global__ void scatter_kernel(const float* __restrict__ x,
                               const int* __restrict__ src,
                               const int* __restrict__ dst,
                               const float* __restrict__ gcn_w, int E8) {
    int i = blockIdx.x * blockDim.x + threadIdx.x;
    if (i >= E8) return;
    float w = __ldg(gcn_w);
    int4 s0 = reinterpret_cast<const int4*>(src)[2 * i];
    int4 s1 = reinterpret_cast<const int4*>(src)[2 * i + 1];
    int4 d0 = reinterpret_cast<const int4*>(dst)[2 * i];
    int4 d1 = reinterpret_cast<const int4*>(dst)[2 * i + 1];
    scat1(x, w, s0.x, d0.x);
    scat1(x, w, s0.y, d0.y);
    scat1(x, w, s0.z, d0.z);
    scat1(x, w, s0.w, d0.w);
    scat1(x, w, s1.x, d1.x);
    scat1(x, w, s1.y, d1.y);
    scat1(x, w, s1.z, d1.z);
    scat1(x, w, s1.w, d1.w);
}

__global__ void scatter_tail_kernel(const float* __restrict__ x,
                                    const int* __restrict__ src,
                                    const int* __restrict__ dst,
                                    const float* __restrict__ gcn_w,
                                    int start, int E) {
    int i = start + blockIdx.x * blockDim.x + threadIdx.x;
    if (i >= E) return;
    scat1(x, __ldg(gcn_w), src[i], dst[i]);
}

__global__ void relu_round_kernel(int n4) {
    float4* p = reinterpret_cast<float4*>(g_agg);
    int idx = blockIdx.x * blockDim.x + threadIdx.x;
    int stride = gridDim.x * blockDim.x;
    for (int i = idx; i < n4; i += stride) {
        float4 v = p[i];
        v.x = to_tf32(fmaxf(v.x, 0.f));
        v.y = to_tf32(fmaxf(v.y, 0.f));
        v.z = to_tf32(fmaxf(v.z, 0.f));
        v.w = to_tf32(fmaxf(v.w, 0.f));
        p[i] = v;
    }
}

__global__ void transpose_w1(const float* __restrict__ W) {  // [978][2048] -> [2048][992]
    __shared__ float t[32][33];
    int kb = blockIdx.x * 32, nb = blockIdx.y * 32;
    int tx = threadIdx.x, ty = threadIdx.y;
    for (int i = ty; i < 32; i += 8) {
        int k = kb + i;
        float v = (k < N_GENES) ? W[(size_t)k * HID + (nb + tx)] : 0.f;
        t[i][tx] = to_tf32(v);
    }
    __syncthreads();
    for (int i = ty; i < 32; i += 8)
        g_W1t[(size_t)(nb + i) * AKP + (kb + tx)] = t[tx][i];
}

__global__ void transpose_w2(const float* __restrict__ W) {  // [2048][100] -> [128][2048]
    __shared__ float t[32][33];
    int kb = blockIdx.x * 32, nb = blockIdx.y * 32;
    int tx = threadIdx.x, ty = threadIdx.y;
    for (int i = ty; i < 32; i += 8) {
        int n = nb + tx;
        float v = (n < OUTD) ? W[(size_t)(kb + i) * OUTD + n] : 0.f;
        t[i][tx] = to_tf32(v);
    }
    __syncthreads();
    for (int i = ty; i < 32; i += 8)
        g_W2t[(size_t)(nb + i) * HID + (kb + tx)] = t[tx][i];
}

__global__ void out_init_kernel(float* __restrict__ out, const float* __restrict__ b2, int total) {
    int i = blockIdx.x * blockDim.x + threadIdx.x;
    if (i < total) out[i] = b2[i % OUTD];
}

// ===========================================================================
// Unified tf32 mma.sync GEMM: 128x128 CTA tile, 3-stage cp.async,
// 256 threads (8 warps, 4M x 2N, warp tile 32x64), 2 CTAs/SM.
//   EPI=1: C = g_h, v = tf32(relu(acc + bias))     (GEMM1: A=g_agg, B=g_W1t)
//   EPI=2: atomicAdd into Cout, guard n < OUTD     (GEMM2: A=g_h,   B=g_W2t)
// ===========================================================================
template<int EPI, int LDA_, int LDB_>
__global__ void __launch_bounds__(256, 2)
mma_gemm(const float* __restrict__ bias, float* __restrict__ Cout, int kIters) {
    constexpr int BMp = 128, BNp = 128, MT = 2;
    const float* A = (EPI == 1) ? g_agg : g_h;
    const float* B = (EPI == 1) ? g_W1t : g_W2t;

    extern __shared__ float smem[];
    constexpr uint32_t AS_B    = BMp * BKP * 4;
    constexpr uint32_t BS_B    = BNp * BKP * 4;
    constexpr uint32_t STAGE_B = AS_B + BS_B;

    const int tid  = threadIdx.x;
    const int wid  = tid >> 5;
    const int lane = tid & 31;
    const int bm = blockIdx.y * BMp;
    const int bn = blockIdx.x * BNp;
    const int k0base = blockIdx.z * kIters * BK;

    const int m0w = (wid >> 1) * (BMp / 4);
    const int n0w = (wid & 1) * 64;
    const int grp = lane >> 2, t4 = lane & 3;

    const uint32_t s_base = smem_u32(smem);

    const int tI = lane >> 3, rI = lane & 7;
    const uint32_t a_off = (uint32_t)((m0w + (tI & 1) * 8 + rI) * BKP + (tI >> 1) * 4) * 4;
    const uint32_t b_off = (uint32_t)((n0w + (tI >> 1) * 8 + rI) * BKP + (tI & 1) * 4) * 4;

    float acc[MT][8][4];
    #pragma unroll
    for (int a = 0; a < MT; a++)
        #pragma unroll
        for (int b = 0; b < 8; b++)
            #pragma unroll
            for (int c = 0; c < 4; c++) acc[a][b][c] = 0.f;

    auto load_tile = [&](int stage, int k0) {
        uint32_t sa = s_base + stage * STAGE_B;
        #pragma unroll
        for (int i = 0; i < BMp / 32; i++) {
            int idx = tid + i * 256;
            int m = idx >> 3, kq = idx & 7;
            cp16(sa + (uint32_t)(m * BKP + kq * 4) * 4,
                 A + (size_t)(bm + m) * LDA_ + k0 + kq * 4);
        }
        uint32_t sb = sa + AS_B;
        #pragma unroll
        for (int i = 0; i < BNp / 32; i++) {
            int idx = tid + i * 256;
            int n = idx >> 3, kq = idx & 7;
            cp16(sb + (uint32_t)(n * BKP + kq * 4) * 4,
                 B + (size_t)(bn + n) * LDB_ + k0 + kq * 4);
        }
    };

    // prologue: fill stages 0..NSTG-2
    #pragma unroll
    for (int p = 0; p < NSTG - 1; ++p) {
        if (p < kIters) load_tile(p, k0base + p * BK);
        asm volatile("cp.async.commit_group;");
    }

    for (int it = 0; it < kIters; ++it) {
        int st = it % NSTG;
        asm volatile("cp.async.wait_group %0;" :: "n"(NSTG - 2));
        __syncthreads();

        #pragma unroll
        for (int ks = 0; ks < 4; ++ks) {
            uint32_t af[MT][4];
            #pragma unroll
            for (int mt = 0; mt < MT; ++mt)
                ldsm4(s_base + st * STAGE_B + a_off + (uint32_t)(mt * 16 * BKP + ks * 8) * 4,
                      af[mt][0], af[mt][1], af[mt][2], af[mt][3]);
            uint32_t bf[4][4];
            #pragma unroll
            for (int np = 0; np < 4; ++np)
                ldsm4(s_base + st * STAGE_B + AS_B + b_off + (uint32_t)(np * 16 * BKP + ks * 8) * 4,
                      bf[np][0], bf[np][1], bf[np][2], bf[np][3]);
            #pragma unroll
            for (int mt = 0; mt < MT; ++mt)
                #pragma unroll
                for (int nt = 0; nt < 8; ++nt)
                    mma_tf32(acc[mt][nt], af[mt],
                             bf[nt >> 1][(nt & 1) * 2], bf[nt >> 1][(nt & 1) * 2 + 1]);
        }

        __syncthreads();
        if (it + NSTG - 1 < kIters)
            load_tile((it + NSTG - 1) % NSTG, k0base + (it + NSTG - 1) * BK);
        asm volatile("cp.async.commit_group;");
    }

    // epilogue
    #pragma unroll
    for (int mt = 0; mt < MT; ++mt) {
        int gm0 = bm + m0w + mt * 16 + grp;
        #pragma unroll
        for (int nt = 0; nt < 8; ++nt) {
            int gn = bn + n0w + nt * 8 + t4 * 2;
            if (EPI == 1) {
                float b0v = bias[gn], b1v = bias[gn + 1];
                float v0 = to_tf32(fmaxf(acc[mt][nt][0] + b0v, 0.f));
                float v1 = to_tf32(fmaxf(acc[mt][nt][1] + b1v, 0.f));
                float v2 = to_tf32(fmaxf(acc[mt][nt][2] + b0v, 0.f));
                float v3 = to_tf32(fmaxf(acc[mt][nt][3] + b1v, 0.f));
                *reinterpret_cast<float2*>(&g_h[(size_t)gm0 * HID + gn])       = make_float2(v0, v1);
                *reinterpret_cast<float2*>(&g_h[(size_t)(gm0 + 8) * HID + gn]) = make_float2(v2, v3);
            } else {
                if (gn < OUTD) {   // gn even, so gn+1 < OUTD too
                    atomicAdd(&Cout[(size_t)gm0 * OUTD + gn],           acc[mt][nt][0]);
                    atomicAdd(&Cout[(size_t)gm0 * OUTD + gn + 1],       acc[mt][nt][1]);
                    atomicAdd(&Cout[(size_t)(gm0 + 8) * OUTD + gn],     acc[mt][nt][2]);
                    atomicAdd(&Cout[(size_t)(gm0 + 8) * OUTD + gn + 1], acc[mt][nt][3]);
                }
            }
        }
    }
}

// ===========================================================================
// launch
// ===========================================================================
extern "C" void kernel_launch(void* const* d_in, const int* in_sizes, int n_in,
                              void* d_out, int out_size) {
    const float* inputs = (const float*)d_in[0];
    const int*   edges  = (const int*)d_in[1];    // int32 (JAX x64 disabled)
    const float* gcn_w  = (const float*)d_in[2];
    const float* gcn_b  = (const float*)d_in[3];
    const float* W1     = (const float*)d_in[4];
    const float* b1     = (const float*)d_in[5];
    const float* W2     = (const float*)d_in[6];
    const float* b2     = (const float*)d_in[7];
    float*       out    = (float*)d_out;

    const int E = in_sizes[1] / 2;
    const int* src = edges;
    const int* dst = edges + E;

    constexpr int G_SMEM = NSTG * (128 * BKP + 128 * BKP) * 4;   // 110592

    cudaFuncSetAttribute(mma_gemm<1, AKP, AKP>,
                         cudaFuncAttributeMaxDynamicSharedMemorySize, G_SMEM);
    cudaFuncSetAttribute(mma_gemm<2, HID, HID>,
                         cudaFuncAttributeMaxDynamicSharedMemorySize, G_SMEM);

    // 1) agg = bias (padded)
    init_agg_kernel<<<1184, 256>>>(gcn_b, MROWS * AKP / 4);

    // 2) scatter (8 edges per thread)
    {
        int E8 = E / 8;
        if (E8 > 0)
            scatter_kernel<<<(E8 + 255) / 256, 256>>>(inputs, src, dst, gcn_w, E8);
        if (E - E8 * 8 > 0)
            scatter_tail_kernel<<<1, 256>>>(inputs, src, dst, gcn_w, E8 * 8, E);
    }

    // 3) relu + tf32 round on agg
    relu_round_kernel<<<1184, 256>>>(MROWS * AKP / 4);

    // 4) weight prep
    transpose_w1<<<dim3(AKP / 32, HID / 32), dim3(32, 8)>>>(W1);
    transpose_w2<<<dim3(HID / 32, OUTP / 32), dim3(32, 8)>>>(W2);

    // 5) out = b2 (broadcast) for split-K accumulation
    out_init_kernel<<<(MROWS * OUTD + 255) / 256, 256>>>(out, b2, MROWS * OUTD);

    // 6) GEMM1: h = tf32(relu(relu(agg) @ W1 + b1))   grid (16, 64), occ 2
    mma_gemm<1, AKP, AKP>
        <<<dim3(HID / 128, MROWS / 128), 256, G_SMEM>>>(b1, nullptr, AKP / BK);

    // 7) GEMM2: out += h @ W2   split-K=4, grid (1, 64, 4) = 256 CTAs, occ 2
    mma_gemm<2, HID, HID>
        <<<dim3(1, MROWS / 128, 4), 256, G_SMEM>>>(nullptr, out, HID / BK / 4);
}